// round 3
// baseline (speedup 1.0000x reference)
#include <cuda_runtime.h>

#define NB      11
#define NBINS   1331        // 11^3
#define ITER    20
#define TPB     256
#define NWARP   8           // warps per block
#define HBLOCKS 512         // 512*256 = 2^17 threads -> 128 pixels/thread exactly
#define HPAD    1344        // padded per-warp histogram stride (u16 elements)

__device__ int   g_hist[NBINS];
__device__ float g_cut01[3][NB];    // transformed cuts in [0,1]
__device__ float g_cut255[3][NB];   // transformed cuts * 255

// ---------------------------------------------------------------------------
// K1: zero global histogram, sort+clip+pin the three 11-element cut arrays.
// ---------------------------------------------------------------------------
__global__ void prep_kernel(const float* __restrict__ r_cut,
                            const float* __restrict__ g_cut,
                            const float* __restrict__ b_cut) {
    int t = threadIdx.x;
    for (int i = t; i < NBINS; i += blockDim.x) g_hist[i] = 0;
    if (t < 3) {
        const float* src = (t == 0) ? r_cut : (t == 1) ? g_cut : b_cut;
        float v[NB];
        for (int i = 0; i < NB; i++) v[i] = src[i];
        for (int i = 1; i < NB; i++) {          // insertion sort ascending
            float key = v[i];
            int j = i - 1;
            while (j >= 0 && v[j] > key) { v[j + 1] = v[j]; j--; }
            v[j + 1] = key;
        }
        for (int i = 0; i < NB; i++) v[i] = fminf(fmaxf(v[i], 0.0f), 1.0f);
        v[0] = 0.0f;
        v[NB - 1] = 1.0f;
        for (int i = 0; i < NB; i++) {
            g_cut01[t][i]  = v[i];
            g_cut255[t][i] = v[i] * 255.0f;
        }
    }
}

// ---------------------------------------------------------------------------
// K2: histogram with ZERO atomics on the hot path.
// Per-warp private u16 histograms in shared memory; __match_any_sync dedups
// equal bins within the warp so the group leader can do a plain (non-atomic)
// u16 read-modify-write. Distinct leader bins => distinct addresses => safe.
// Block flush sums the 8 warp copies and does one global atomicAdd per bin.
// ---------------------------------------------------------------------------
__global__ void __launch_bounds__(TPB) hist_kernel(const float4* __restrict__ x, int n) {
    __shared__ unsigned short wh[NWARP][HPAD];

    for (int i = threadIdx.x; i < NWARP * HPAD; i += TPB)
        (&wh[0][0])[i] = 0;

    float rc[NB], gc[NB], bc[NB];
#pragma unroll
    for (int i = 0; i < NB; i++) {
        rc[i] = g_cut255[0][i];
        gc[i] = g_cut255[1][i];
        bc[i] = g_cut255[2][i];
    }
    __syncthreads();

    const int lane = threadIdx.x & 31;
    unsigned short* __restrict__ myh = wh[threadIdx.x >> 5];

    const int stride = TPB * gridDim.x;
    for (int base = blockIdx.x * TPB + threadIdx.x; ; base += stride) {
        bool valid = (base < n);
        unsigned act = __ballot_sync(0xffffffffu, valid);
        if (act == 0) break;
        if (valid) {
            float4 p = x[base];
            int ri = 0, gi = 0, bi = 0;
#pragma unroll
            for (int j = 0; j < NB; j++) {
                ri += (rc[j] < p.x);
                gi += (gc[j] < p.y);
                bi += (bc[j] < p.z);
            }
            ri += 10; if (ri >= 11) ri -= 11;   // (iv-1) mod 11
            gi += 10; if (gi >= 11) gi -= 11;
            bi += 10; if (bi >= 11) bi -= 11;
            int bin = ri * 121 + gi * 11 + bi;

            unsigned mask = __match_any_sync(act, bin);
            int leader = __ffs(mask) - 1;
            if (lane == leader) {
                myh[bin] = (unsigned short)(myh[bin] + __popc(mask));
            }
        }
        if (act != 0xffffffffu) break;          // tail round done
    }
    __syncthreads();

    for (int i = threadIdx.x; i < NBINS; i += TPB) {
        int s = 0;
#pragma unroll
        for (int w = 0; w < NWARP; w++) s += wh[w][i];
        if (s) atomicAdd(&g_hist[i], s);
    }
}

// ---------------------------------------------------------------------------
// K3: top-20 stable selection (count desc, bin asc) + color computation.
// ---------------------------------------------------------------------------
__global__ void __launch_bounds__(512) topk_kernel(float* __restrict__ out) {
    __shared__ unsigned long long keys[NBINS];
    __shared__ unsigned long long warpmax[16];
    __shared__ int top[ITER];
    int t = threadIdx.x;

    for (int i = t; i < NBINS; i += blockDim.x) {
        unsigned long long c = (unsigned long long)(unsigned int)g_hist[i];
        keys[i] = ((c << 11) | (unsigned long long)(1330 - i)) + 1ull;
    }
    __syncthreads();

    for (int it = 0; it < ITER; it++) {
        unsigned long long m = 0;
        for (int i = t; i < NBINS; i += blockDim.x) {
            unsigned long long k = keys[i];
            m = (k > m) ? k : m;
        }
#pragma unroll
        for (int o = 16; o > 0; o >>= 1) {
            unsigned long long k = __shfl_xor_sync(0xffffffffu, m, o);
            m = (k > m) ? k : m;
        }
        if ((t & 31) == 0) warpmax[t >> 5] = m;
        __syncthreads();
        if (t < 32) {
            unsigned long long w = (t < 16) ? warpmax[t] : 0ull;
#pragma unroll
            for (int o = 16; o > 0; o >>= 1) {
                unsigned long long k = __shfl_xor_sync(0xffffffffu, w, o);
                w = (k > w) ? k : w;
            }
            if (t == 0) {
                int bin = 1330 - (int)((w - 1ull) & 0x7FFull);
                top[it] = bin;
                keys[bin] = 0ull;
            }
        }
        __syncthreads();
    }

    if (t < ITER) {
        int bin = top[t];
        int r = bin / 121;
        int g = (bin / 11) % 11;
        int b = bin % 11;
        r = min(r, NB - 2);
        g = min(g, NB - 2);
        b = min(b, NB - 2);
        float rv = 255.0f * (float)r / (float)NB + (g_cut01[0][r + 1] - g_cut01[0][r]) * 255.0f / 2.0f;
        float gv = 255.0f * (float)g / (float)NB + (g_cut01[1][g + 1] - g_cut01[1][g]) * 255.0f / 2.0f;
        float bv = 255.0f * (float)b / (float)NB + (g_cut01[2][b + 1] - g_cut01[2][b]) * 255.0f / 2.0f;
        out[t * 4 + 0] = rv;
        out[t * 4 + 1] = gv;
        out[t * 4 + 2] = bv;
        out[t * 4 + 3] = 255.0f;
    }
}

// ---------------------------------------------------------------------------
extern "C" void kernel_launch(void* const* d_in, const int* in_sizes, int n_in,
                              void* d_out, int out_size) {
    const float* x  = (const float*)d_in[0];
    const float* rc = (const float*)d_in[1];
    const float* gc = (const float*)d_in[2];
    const float* bc = (const float*)d_in[3];
    int n = in_sizes[0] / 4;   // number of pixels (float4 elements)

    prep_kernel<<<1, 256>>>(rc, gc, bc);
    hist_kernel<<<HBLOCKS, TPB>>>((const float4*)x, n);
    topk_kernel<<<1, 512>>>((float*)d_out);
}

// round 4
// speedup vs baseline: 1.3210x; 1.3210x over previous
#include <cuda_runtime.h>

#define NB     11
#define NBINS  1331        // 11^3
#define ITER   20
#define TPB    64          // 2 warps per block
#define NCOPY  16          // histogram copies per block (8 per warp)
#define GRID   740         // 5 blocks/SM * 148 SMs = one full wave
#define NGC    8           // global histogram copies

__device__ int          g_histG[NGC][NBINS];  // zero-init; re-zeroed by last block
__device__ unsigned int g_done;               // zero-init; reset by last block

__global__ void __launch_bounds__(TPB) fused_kernel(
    const float4* __restrict__ x, int n,
    const float*  __restrict__ r_cut,
    const float*  __restrict__ g_cut,
    const float*  __restrict__ b_cut,
    float* __restrict__ out)
{
    __shared__ __align__(16) unsigned short wh[NBINS][NCOPY];   // 42592 B
    __shared__ float s_cut01[3][NB];
    __shared__ float s_cut255[3][NB];
    __shared__ unsigned long long s_wmax[2];
    __shared__ int s_top[ITER];
    __shared__ int s_last;

    const int t    = threadIdx.x;
    const int lane = t & 31;
    const int wid  = t >> 5;

    // ---- cuts: clip+rank-sort (order of clip/sort commutes as a multiset) ----
    if (t < 33) {
        int c = t / NB, j = t - c * NB;
        const float* src = (c == 0) ? r_cut : (c == 1) ? g_cut : b_cut;
        float vj = fminf(fmaxf(src[j], 0.0f), 1.0f);
        int rank = 0;
        for (int k = 0; k < NB; k++) {
            float vk = fminf(fmaxf(src[k], 0.0f), 1.0f);
            rank += (vk < vj) || (vk == vj && k < j);
        }
        s_cut01[c][rank] = vj;
    }
    // zero private histograms
    {
        uint4* w4 = (uint4*)&wh[0][0];
        const int n4 = (NBINS * NCOPY * 2) / 16;   // 2662
        for (int i = t; i < n4; i += TPB) w4[i] = make_uint4(0, 0, 0, 0);
    }
    __syncthreads();
    if (t < 33) {
        int c = t / NB, j = t - c * NB;
        float v = s_cut01[c][j];
        if (j == 0)      v = 0.0f;
        if (j == NB - 1) v = 1.0f;
        s_cut01[c][j]  = v;
        s_cut255[c][j] = v * 255.0f;
    }
    __syncthreads();

    // cuts in registers. cut[10]*255 == 255 and x < 255 always (x = u*255, u<1),
    // so the j==10 compare is always false -> only 10 compares per channel.
    float rc[NB - 1], gc[NB - 1], bc[NB - 1];
#pragma unroll
    for (int i = 0; i < NB - 1; i++) {
        rc[i] = s_cut255[0][i];
        gc[i] = s_cut255[1][i];
        bc[i] = s_cut255[2][i];
    }

    const int copy = (wid << 3) | (lane & 7);   // 8 copies per warp
    const int q    = lane >> 3;                  // position within 4-lane share group
    unsigned short* whf = &wh[0][0];

    const int gtid   = blockIdx.x * TPB + t;
    const int stride = GRID * TPB;
    const int full   = n / stride;

#define BIN_OF(p, bin) do {                                                    \
        int ri = 0, gi = 0, bi = 0;                                            \
        _Pragma("unroll")                                                      \
        for (int j = 0; j < NB - 1; j++) {                                     \
            ri += (rc[j] < (p).x);                                             \
            gi += (gc[j] < (p).y);                                             \
            bi += (bc[j] < (p).z);                                             \
        }                                                                      \
        ri -= 1; if (ri < 0) ri += NB;  /* (iv-1) mod 11, iv in [0,10] */      \
        gi -= 1; if (gi < 0) gi += NB;                                         \
        bi -= 1; if (bi < 0) bi += NB;                                         \
        (bin) = (ri * NB + gi) * NB + bi;                                      \
    } while (0)

#define DEPOSIT(bin, valid) do {                                               \
        int _b   = (bin);                                                      \
        int _b8  = __shfl_xor_sync(0xffffffffu, _b, 8);                        \
        int _b16 = __shfl_xor_sync(0xffffffffu, _b, 16);                       \
        int _b24 = __shfl_xor_sync(0xffffffffu, _b, 24);                       \
        int _e8  = (_b == _b8), _e16 = (_b == _b16), _e24 = (_b == _b24);      \
        int _add = 1 + _e8 + _e16 + _e24;                                      \
        bool _ldr = !((_e8 && (q & 1)) || (_e16 && (q & 2)) || (_e24 && (q & 2))); \
        if ((valid) && _ldr) {                                                 \
            unsigned short* _p = whf + _b * NCOPY + copy;                      \
            *_p = (unsigned short)(*_p + _add);                                \
        }                                                                      \
    } while (0)

    // main loop: every thread does exactly `full` unguarded rounds
#pragma unroll 2
    for (int r = 0; r < full; r++) {
        float4 p = x[gtid + (long long)r * stride];
        int bin;
        BIN_OF(p, bin);
        DEPOSIT(bin, true);
    }
    // single guarded tail round
    {
        long long idx = (long long)gtid + (long long)full * stride;
        bool valid = idx < n;
        int bin = -1 - lane;            // unique per lane -> no false collisions
        if (valid) {
            float4 p = x[idx];
            BIN_OF(p, bin);
        }
        DEPOSIT(bin, valid);
    }
    __syncthreads();

    // ---- flush block-private histogram to one of NGC global copies ----
    int* gdst = g_histG[blockIdx.x & (NGC - 1)];
    for (int i = t; i < NBINS; i += TPB) {
        const unsigned short* row = whf + i * NCOPY;
        int s = 0;
#pragma unroll
        for (int c2 = 0; c2 < NCOPY; c2++) s += row[c2];
        if (s) atomicAdd(&gdst[i], s);
    }
    __threadfence();
    if (t == 0) {
        unsigned int ticket = atomicAdd(&g_done, 1u);
        s_last = (ticket == GRID - 1);
    }
    __syncthreads();
    if (!s_last) return;

    // ---- last block: top-20 stable selection + output + state reset ----
    __threadfence();   // acquire side of the ticket handshake
    unsigned long long* keys = (unsigned long long*)whf;   // reuse smem
    for (int i = t; i < NBINS; i += TPB) {
        unsigned int c = 0;
#pragma unroll
        for (int k = 0; k < NGC; k++) c += (unsigned int)__ldcg(&g_histG[k][i]);
        keys[i] = (((unsigned long long)c << 11) |
                   (unsigned long long)(1330 - i)) + 1ull;
#pragma unroll
        for (int k = 0; k < NGC; k++) g_histG[k][i] = 0;    // reset for next replay
    }
    __syncthreads();

    for (int it = 0; it < ITER; it++) {
        unsigned long long m = 0;
        for (int i = t; i < NBINS; i += TPB) {
            unsigned long long k = keys[i];
            m = (k > m) ? k : m;
        }
#pragma unroll
        for (int o = 16; o > 0; o >>= 1) {
            unsigned long long k = __shfl_xor_sync(0xffffffffu, m, o);
            m = (k > m) ? k : m;
        }
        if (lane == 0) s_wmax[wid] = m;
        __syncthreads();
        if (t == 0) {
            unsigned long long w = (s_wmax[0] > s_wmax[1]) ? s_wmax[0] : s_wmax[1];
            int bin = 1330 - (int)((w - 1ull) & 0x7FFull);
            s_top[it] = bin;
            keys[bin] = 0ull;
        }
        __syncthreads();
    }

    if (t < ITER) {
        int bin = s_top[t];
        int r = bin / 121;
        int g = (bin / 11) % 11;
        int b = bin % 11;
        r = min(r, NB - 2);
        g = min(g, NB - 2);
        b = min(b, NB - 2);
        float rv = 255.0f * (float)r / (float)NB + (s_cut01[0][r + 1] - s_cut01[0][r]) * 255.0f / 2.0f;
        float gv = 255.0f * (float)g / (float)NB + (s_cut01[1][g + 1] - s_cut01[1][g]) * 255.0f / 2.0f;
        float bv = 255.0f * (float)b / (float)NB + (s_cut01[2][b + 1] - s_cut01[2][b]) * 255.0f / 2.0f;
        out[t * 4 + 0] = rv;
        out[t * 4 + 1] = gv;
        out[t * 4 + 2] = bv;
        out[t * 4 + 3] = 255.0f;
    }
    if (t == 0) g_done = 0;   // reset ticket for next replay
}

// ---------------------------------------------------------------------------
extern "C" void kernel_launch(void* const* d_in, const int* in_sizes, int n_in,
                              void* d_out, int out_size) {
    const float* x  = (const float*)d_in[0];
    const float* rc = (const float*)d_in[1];
    const float* gc = (const float*)d_in[2];
    const float* bc = (const float*)d_in[3];
    int n = in_sizes[0] / 4;   // number of pixels

    fused_kernel<<<GRID, TPB>>>((const float4*)x, n, rc, gc, bc, (float*)d_out);
}

// round 5
// speedup vs baseline: 1.4604x; 1.1055x over previous
#include <cuda_runtime.h>

#define NB     11
#define NBINS  1331        // 11^3
#define ITER   20
#define TPB    32          // one warp per block
#define BPSM   10
#define GRID   (148 * BPSM)   // 1480 blocks = one wave
#define NGC    8           // global histogram copies
#define CHUNK  126         // u8 flush period (max 2/iter/copy -> 252 <= 255)

__device__ int          g_histG[NGC][NBINS];  // zero-init; re-zeroed by last block
__device__ unsigned int g_done;               // zero-init; reset by last block

__global__ void __launch_bounds__(TPB, BPSM) fused_kernel(
    const float4* __restrict__ x, int n,
    const float*  __restrict__ r_cut,
    const float*  __restrict__ g_cut,
    const float*  __restrict__ b_cut,
    float* __restrict__ out)
{
    // per-warp u8 histogram: 16 copies, lanes l and l+16 share copy (lane&15)
    __shared__ __align__(16) unsigned char wh[NBINS * 16];   // 21296 B
    __shared__ float s_cut01[3][NB];
    __shared__ float s_cut255[3][NB];
    __shared__ int s_top[ITER];
    __shared__ int s_last;

    const int lane = threadIdx.x;

    // ---- cuts: clip + rank-sort (clip/sort commute as a multiset) ----
    for (int item = lane; item < 33; item += TPB) {
        int c = item / NB, j = item - c * NB;
        const float* src = (c == 0) ? r_cut : (c == 1) ? g_cut : b_cut;
        float vj = fminf(fmaxf(src[j], 0.0f), 1.0f);
        int rank = 0;
        for (int k = 0; k < NB; k++) {
            float vk = fminf(fmaxf(src[k], 0.0f), 1.0f);
            rank += (vk < vj) || (vk == vj && k < j);
        }
        s_cut01[c][rank] = vj;
    }
    // zero private histogram (1331 uint4 = 21296 B)
    {
        uint4* w4 = (uint4*)wh;
        for (int i = lane; i < NBINS; i += TPB) w4[i] = make_uint4(0, 0, 0, 0);
    }
    __syncwarp();
    for (int item = lane; item < 33; item += TPB) {
        int c = item / NB, j = item - c * NB;
        float v = s_cut01[c][j];
        if (j == 0)      v = 0.0f;
        if (j == NB - 1) v = 1.0f;
        s_cut01[c][j]  = v;
        s_cut255[c][j] = v * 255.0f;
    }
    __syncwarp();

    // cut[10]*255 == 255 and x = u*255 with u<1 -> x < 255 always in fp32,
    // so the j==10 compare is always false: 10 compares per channel.
    float rc[NB - 1], gc[NB - 1], bc[NB - 1];
#pragma unroll
    for (int i = 0; i < NB - 1; i++) {
        rc[i] = s_cut255[0][i];
        gc[i] = s_cut255[1][i];
        bc[i] = s_cut255[2][i];
    }

    const int copy   = lane & 15;
    const int gtid   = blockIdx.x * TPB + lane;
    const int stride = GRID * TPB;
    const int full   = n / stride;
    int* gdst = g_histG[blockIdx.x & (NGC - 1)];

#define BIN_OF(p, bin) do {                                                    \
        int ri = 0, gi = 0, bi = 0;                                            \
        _Pragma("unroll")                                                      \
        for (int j = 0; j < NB - 1; j++) {                                     \
            ri += (rc[j] < (p).x);                                             \
            gi += (gc[j] < (p).y);                                             \
            bi += (bc[j] < (p).z);                                             \
        }                                                                      \
        ri -= 1; if (ri < 0) ri += NB;   /* (iv-1) mod 11, iv in [0,10] */     \
        gi -= 1; if (gi < 0) gi += NB;                                         \
        bi -= 1; if (bi < 0) bi += NB;                                         \
        (bin) = (ri * NB + gi) * NB + bi;                                      \
    } while (0)

    // one shfl dedup: lanes l and l+16 share a copy
#define DEPOSIT(bin, valid) do {                                               \
        int _b  = (bin);                                                       \
        int _ob = __shfl_xor_sync(0xffffffffu, _b, 16);                        \
        int _same = (_b == _ob);                                               \
        int _add  = 1 + _same;                                                 \
        bool _ldr = !(_same && (lane & 16));                                   \
        if ((valid) && _ldr) {                                                 \
            unsigned char* _p = wh + _b * 16 + copy;                           \
            *_p = (unsigned char)(*_p + _add);                                 \
        }                                                                      \
    } while (0)

    // flush u8 copies into global, zeroing in place; rotated word index keeps
    // the LDS/STS pattern bank-conflict-free ((5*lane+k) mod 32 distinct).
#define FLUSH() do {                                                           \
        __syncwarp();                                                          \
        for (int _base = 0; _base < NBINS; _base += TPB) {                     \
            int _bin = _base + lane;                                           \
            if (_bin < NBINS) {                                                \
                unsigned _s = 0;                                               \
                _Pragma("unroll")                                              \
                for (int _k = 0; _k < 4; _k++) {                               \
                    int _w = (lane + _k) & 3;                                  \
                    unsigned* _wp = (unsigned*)(wh + _bin * 16 + _w * 4);      \
                    unsigned _word = *_wp;                                     \
                    *_wp = 0u;                                                 \
                    _s = __dp4a(_word, 0x01010101u, _s);                       \
                }                                                              \
                if (_s) atomicAdd(&gdst[_bin], (int)_s);                       \
            }                                                                  \
        }                                                                      \
        __syncwarp();                                                          \
    } while (0)

    // ---- main loop: chunks of CHUNK iterations, flush between chunks ----
    int r = 0;
    while (r < full) {
        int end = min(r + CHUNK, full);
#pragma unroll 6
        for (; r < end; r++) {
            float4 p = __ldcs(&x[gtid + r * stride]);
            int bin;
            BIN_OF(p, bin);
            DEPOSIT(bin, true);
        }
        FLUSH();
    }
    // guarded tail round (array freshly zeroed; adds <= 2 per copy)
    {
        int idx = gtid + full * stride;
        bool valid = idx < n;
        int bin = -1 - lane;            // unique per lane -> no false pair-match
        if (valid) {
            float4 p = __ldcs(&x[idx]);
            BIN_OF(p, bin);
        }
        DEPOSIT(bin, valid);
        FLUSH();
    }

    // ---- ticket: last block does top-k ----
    __threadfence();
    if (lane == 0) s_last = (atomicAdd(&g_done, 1u) == GRID - 1);
    __syncwarp();
    if (!s_last) return;
    __threadfence();

    unsigned long long* keys = (unsigned long long*)wh;   // 10648 B, fits
    for (int i = lane; i < NBINS; i += TPB) {
        unsigned int c = 0;
#pragma unroll
        for (int k = 0; k < NGC; k++) c += (unsigned int)__ldcg(&g_histG[k][i]);
        keys[i] = (((unsigned long long)c << 11) |
                   (unsigned long long)(1330 - i)) + 1ull;
#pragma unroll
        for (int k = 0; k < NGC; k++) g_histG[k][i] = 0;   // reset for replay
    }
    __syncwarp();

    for (int it = 0; it < ITER; it++) {
        unsigned long long m = 0;
        for (int i = lane; i < NBINS; i += TPB) {
            unsigned long long k = keys[i];
            m = (k > m) ? k : m;
        }
#pragma unroll
        for (int o = 16; o > 0; o >>= 1) {
            unsigned long long k = __shfl_xor_sync(0xffffffffu, m, o);
            m = (k > m) ? k : m;
        }
        m = __shfl_sync(0xffffffffu, m, 0);
        int bin = 1330 - (int)((m - 1ull) & 0x7FFull);
        if (lane == 0) {
            s_top[it] = bin;
            keys[bin] = 0ull;
        }
        __syncwarp();
    }

    if (lane < ITER) {
        int bin = s_top[lane];
        int r2 = bin / 121;
        int g2 = (bin / 11) % 11;
        int b2 = bin % 11;
        r2 = min(r2, NB - 2);
        g2 = min(g2, NB - 2);
        b2 = min(b2, NB - 2);
        float rv = 255.0f * (float)r2 / (float)NB + (s_cut01[0][r2 + 1] - s_cut01[0][r2]) * 255.0f / 2.0f;
        float gv = 255.0f * (float)g2 / (float)NB + (s_cut01[1][g2 + 1] - s_cut01[1][g2]) * 255.0f / 2.0f;
        float bv = 255.0f * (float)b2 / (float)NB + (s_cut01[2][b2 + 1] - s_cut01[2][b2]) * 255.0f / 2.0f;
        out[lane * 4 + 0] = rv;
        out[lane * 4 + 1] = gv;
        out[lane * 4 + 2] = bv;
        out[lane * 4 + 3] = 255.0f;
    }
    if (lane == 0) g_done = 0;   // reset ticket for next replay
}

// ---------------------------------------------------------------------------
extern "C" void kernel_launch(void* const* d_in, const int* in_sizes, int n_in,
                              void* d_out, int out_size) {
    const float* x  = (const float*)d_in[0];
    const float* rc = (const float*)d_in[1];
    const float* gc = (const float*)d_in[2];
    const float* bc = (const float*)d_in[3];
    int n = in_sizes[0] / 4;   // number of pixels

    fused_kernel<<<GRID, TPB>>>((const float4*)x, n, rc, gc, bc, (float*)d_out);
}